// round 1
// baseline (speedup 1.0000x reference)
#include <cuda_runtime.h>

#define N_NODES 100000
#define N_EDGES 1600000
#define HIDDEN  128
#define OUT_DIM 400

// Scratch (allocation-free rule: __device__ globals)
__device__ float d_dinv[N_NODES];   // degree, then d^-1/2 in place
__device__ float d_s[N_NODES];      // layer-1 scalar aggregate per node
__device__ float d_t[N_NODES];      // sum of norms over outgoing edges per node
__device__ float d_g[HIDDEN];       // sum_j t[j] * relu(s[j]*W1 + b1)

// ---------------------------------------------------------------------------
// Pass 1: init deg = 1 (self loop), g = 0
__global__ void k_init() {
    int i = blockIdx.x * blockDim.x + threadIdx.x;
    if (i < N_NODES) d_dinv[i] = 1.0f;
    if (i < HIDDEN)  d_g[i] = 0.0f;
}

// Pass 2: degree histogram over destinations (col). 4 edges/thread, int4 loads.
__global__ void k_deg(const int* __restrict__ col4) {
    int i = blockIdx.x * blockDim.x + threadIdx.x;
    if (i < N_EDGES / 4) {
        int4 c = ((const int4*)col4)[i];
        atomicAdd(&d_dinv[c.x], 1.0f);
        atomicAdd(&d_dinv[c.y], 1.0f);
        atomicAdd(&d_dinv[c.z], 1.0f);
        atomicAdd(&d_dinv[c.w], 1.0f);
    }
}

// Pass 3: dinv = rsqrt(deg); seed s,t with the self-loop contribution
__global__ void k_selfloop(const float* __restrict__ x) {
    int i = blockIdx.x * blockDim.x + threadIdx.x;
    if (i < N_NODES) {
        float dv = rsqrtf(d_dinv[i]);
        d_dinv[i] = dv;
        float sl = dv * dv;          // self-loop norm
        d_s[i] = sl * x[i];
        d_t[i] = sl;
    }
}

// Pass 4: main edge pass. norm = dinv[row]*dinv[col];
//         s[col] += norm * x[row];  t[row] += norm
__global__ void k_edges(const int* __restrict__ row4,
                        const int* __restrict__ col4,
                        const float* __restrict__ x) {
    int i = blockIdx.x * blockDim.x + threadIdx.x;
    if (i < N_EDGES / 4) {
        int4 r = ((const int4*)row4)[i];
        int4 c = ((const int4*)col4)[i];

        float n0 = __ldg(&d_dinv[r.x]) * __ldg(&d_dinv[c.x]);
        float n1 = __ldg(&d_dinv[r.y]) * __ldg(&d_dinv[c.y]);
        float n2 = __ldg(&d_dinv[r.z]) * __ldg(&d_dinv[c.z]);
        float n3 = __ldg(&d_dinv[r.w]) * __ldg(&d_dinv[c.w]);

        atomicAdd(&d_s[c.x], n0 * __ldg(&x[r.x]));
        atomicAdd(&d_s[c.y], n1 * __ldg(&x[r.y]));
        atomicAdd(&d_s[c.z], n2 * __ldg(&x[r.z]));
        atomicAdd(&d_s[c.w], n3 * __ldg(&x[r.w]));

        atomicAdd(&d_t[r.x], n0);
        atomicAdd(&d_t[r.y], n1);
        atomicAdd(&d_t[r.z], n2);
        atomicAdd(&d_t[r.w], n3);
    }
}

// Pass 5: g[f] = sum_i t[i] * relu(s[i]*W1[f] + b1[f]).
// One feature per thread (blockDim = 128); tiles of 128 nodes staged in smem.
__global__ void k_accum_g(const float* __restrict__ W1,
                          const float* __restrict__ b1) {
    __shared__ float ss[128];
    __shared__ float st[128];
    int f = threadIdx.x;
    float w  = W1[f];
    float bb = b1[f];
    float acc = 0.0f;

    for (int base = blockIdx.x * 128; base < N_NODES; base += gridDim.x * 128) {
        int idx = base + f;
        __syncthreads();
        if (idx < N_NODES) { ss[f] = d_s[idx]; st[f] = d_t[idx]; }
        else               { ss[f] = 0.0f;     st[f] = 0.0f;     }
        __syncthreads();
#pragma unroll 8
        for (int j = 0; j < 128; j++) {
            acc += st[j] * fmaxf(fmaf(ss[j], w, bb), 0.0f);
        }
    }
    atomicAdd(&d_g[f], acc);
}

// Pass 6: out[k] = b2[k] + (1/N) * sum_f g[f] * W2[f, k]
__global__ void k_out(const float* __restrict__ W2,
                      const float* __restrict__ b2,
                      float* __restrict__ out) {
    __shared__ float gs[HIDDEN];
    if (threadIdx.x < HIDDEN) gs[threadIdx.x] = d_g[threadIdx.x];
    __syncthreads();
    int k = blockIdx.x * blockDim.x + threadIdx.x;
    if (k < OUT_DIM) {
        float acc = 0.0f;
#pragma unroll 8
        for (int f = 0; f < HIDDEN; f++) {
            acc = fmaf(gs[f], W2[f * OUT_DIM + k], acc);
        }
        out[k] = b2[k] + acc * (1.0f / (float)N_NODES);
    }
}

// ---------------------------------------------------------------------------
extern "C" void kernel_launch(void* const* d_in, const int* in_sizes, int n_in,
                              void* d_out, int out_size) {
    const float* x  = (const float*)d_in[0];        // [N, 1]
    const int*   ei = (const int*)d_in[1];          // [2, E]: row then col
    const float* W1 = (const float*)d_in[2];        // [1, 128]
    const float* b1 = (const float*)d_in[3];        // [128]
    const float* W2 = (const float*)d_in[4];        // [128, 400]
    const float* b2 = (const float*)d_in[5];        // [400]
    float* out = (float*)d_out;                     // [400]

    const int* row = ei;
    const int* col = ei + N_EDGES;

    k_init    <<<(N_NODES + 255) / 256, 256>>>();
    k_deg     <<<(N_EDGES / 4 + 255) / 256, 256>>>(col);
    k_selfloop<<<(N_NODES + 255) / 256, 256>>>(x);
    k_edges   <<<(N_EDGES / 4 + 255) / 256, 256>>>(row, col, x);
    k_accum_g <<<296, 128>>>(W1, b1);
    k_out     <<<2, 256>>>(W2, b2, out);
}

// round 2
// speedup vs baseline: 1.0407x; 1.0407x over previous
#include <cuda_runtime.h>

#define N_NODES 100000
#define N_EDGES 1600000
#define HIDDEN  128
#define OUT_DIM 400
#define EPT 8                       // edges per thread in scatter passes

// Scratch (__device__ globals; allocation-free rule)
__device__ float d_deg[N_NODES];    // in-degree (real edges only)
__device__ float d_dinv[N_NODES];   // (deg+1)^-1/2
__device__ float d_a[N_NODES];      // dinv * x
__device__ float d_u[N_NODES];      // sum over out-edges of dinv[col]
__device__ float d_v[N_NODES];      // sum over in-edges of a[row]
__device__ float d_g[HIDDEN];       // sum_i t[i] * relu(s[i]*W1 + b1)

// ---------------------------------------------------------------------------
// Pass 0: zero deg/u/v/g
__global__ void k_zero() {
    int i = blockIdx.x * blockDim.x + threadIdx.x;
    if (i < N_NODES) { d_deg[i] = 0.0f; d_u[i] = 0.0f; d_v[i] = 0.0f; }
    if (i < HIDDEN)  d_g[i] = 0.0f;
}

// Pass 1: in-degree histogram over destinations. 8 edges/thread.
__global__ void k_deg(const int* __restrict__ col) {
    int i = blockIdx.x * blockDim.x + threadIdx.x;
    if (i < N_EDGES / EPT) {
        const int4* c4 = (const int4*)col;
        int4 c0 = c4[2 * i];
        int4 c1 = c4[2 * i + 1];
        atomicAdd(&d_deg[c0.x], 1.0f);
        atomicAdd(&d_deg[c0.y], 1.0f);
        atomicAdd(&d_deg[c0.z], 1.0f);
        atomicAdd(&d_deg[c0.w], 1.0f);
        atomicAdd(&d_deg[c1.x], 1.0f);
        atomicAdd(&d_deg[c1.y], 1.0f);
        atomicAdd(&d_deg[c1.z], 1.0f);
        atomicAdd(&d_deg[c1.w], 1.0f);
    }
}

// Pass 2: dinv = rsqrt(deg+1) (self loop folded in); a = dinv * x
__global__ void k_prep(const float* __restrict__ x) {
    int i = blockIdx.x * blockDim.x + threadIdx.x;
    if (i < N_NODES) {
        float dv = rsqrtf(d_deg[i] + 1.0f);
        d_dinv[i] = dv;
        d_a[i]    = dv * x[i];
    }
}

// Pass 3: main edge pass (factored):
//   v[col] += a[row];  u[row] += dinv[col]
// 8 edges/thread; all 16 gathers issued before the 16 reductions (MLP).
__global__ void k_edges(const int* __restrict__ row,
                        const int* __restrict__ col) {
    int i = blockIdx.x * blockDim.x + threadIdx.x;
    if (i >= N_EDGES / EPT) return;
    const int4* r4 = (const int4*)row;
    const int4* c4 = (const int4*)col;
    int4 r0 = r4[2 * i], r1 = r4[2 * i + 1];
    int4 c0 = c4[2 * i], c1 = c4[2 * i + 1];

    float ar0 = __ldg(&d_a[r0.x]), ar1 = __ldg(&d_a[r0.y]);
    float ar2 = __ldg(&d_a[r0.z]), ar3 = __ldg(&d_a[r0.w]);
    float ar4 = __ldg(&d_a[r1.x]), ar5 = __ldg(&d_a[r1.y]);
    float ar6 = __ldg(&d_a[r1.z]), ar7 = __ldg(&d_a[r1.w]);

    float dc0 = __ldg(&d_dinv[c0.x]), dc1 = __ldg(&d_dinv[c0.y]);
    float dc2 = __ldg(&d_dinv[c0.z]), dc3 = __ldg(&d_dinv[c0.w]);
    float dc4 = __ldg(&d_dinv[c1.x]), dc5 = __ldg(&d_dinv[c1.y]);
    float dc6 = __ldg(&d_dinv[c1.z]), dc7 = __ldg(&d_dinv[c1.w]);

    atomicAdd(&d_v[c0.x], ar0);
    atomicAdd(&d_v[c0.y], ar1);
    atomicAdd(&d_v[c0.z], ar2);
    atomicAdd(&d_v[c0.w], ar3);
    atomicAdd(&d_v[c1.x], ar4);
    atomicAdd(&d_v[c1.y], ar5);
    atomicAdd(&d_v[c1.z], ar6);
    atomicAdd(&d_v[c1.w], ar7);

    atomicAdd(&d_u[r0.x], dc0);
    atomicAdd(&d_u[r0.y], dc1);
    atomicAdd(&d_u[r0.z], dc2);
    atomicAdd(&d_u[r0.w], dc3);
    atomicAdd(&d_u[r1.x], dc4);
    atomicAdd(&d_u[r1.y], dc5);
    atomicAdd(&d_u[r1.z], dc6);
    atomicAdd(&d_u[r1.w], dc7);
}

// Pass 4: finalize s,t on the fly and accumulate
//   s[i] = dinv[i]*(v[i] + dinv[i]*x[i]);  t[i] = dinv[i]*(u[i] + dinv[i])
//   g[f] += sum_i t[i] * relu(s[i]*W1[f] + b1[f])
// blockDim = 128 (one feature per thread); 128-node tiles staged in smem.
__global__ void k_accum_g(const float* __restrict__ x,
                          const float* __restrict__ W1,
                          const float* __restrict__ b1) {
    __shared__ float ss[128];
    __shared__ float st[128];
    int f = threadIdx.x;
    float w  = W1[f];
    float bb = b1[f];
    float acc = 0.0f;

    for (int base = blockIdx.x * 128; base < N_NODES; base += gridDim.x * 128) {
        int idx = base + f;
        __syncthreads();
        if (idx < N_NODES) {
            float dv = d_dinv[idx];
            ss[f] = dv * (d_v[idx] + dv * x[idx]);
            st[f] = dv * (d_u[idx] + dv);
        } else {
            ss[f] = 0.0f;
            st[f] = 0.0f;
        }
        __syncthreads();
#pragma unroll 16
        for (int j = 0; j < 128; j++) {
            acc += st[j] * fmaxf(fmaf(ss[j], w, bb), 0.0f);
        }
    }
    atomicAdd(&d_g[f], acc);
}

// Pass 5: out[k] = b2[k] + (1/N) * sum_f g[f] * W2[f, k]
__global__ void k_out(const float* __restrict__ W2,
                      const float* __restrict__ b2,
                      float* __restrict__ out) {
    __shared__ float gs[HIDDEN];
    if (threadIdx.x < HIDDEN) gs[threadIdx.x] = d_g[threadIdx.x];
    __syncthreads();
    int k = blockIdx.x * blockDim.x + threadIdx.x;
    if (k < OUT_DIM) {
        float acc = 0.0f;
#pragma unroll 16
        for (int f = 0; f < HIDDEN; f++) {
            acc = fmaf(gs[f], W2[f * OUT_DIM + k], acc);
        }
        out[k] = b2[k] + acc * (1.0f / (float)N_NODES);
    }
}

// ---------------------------------------------------------------------------
extern "C" void kernel_launch(void* const* d_in, const int* in_sizes, int n_in,
                              void* d_out, int out_size) {
    const float* x  = (const float*)d_in[0];        // [N, 1]
    const int*   ei = (const int*)d_in[1];          // [2, E]: row then col
    const float* W1 = (const float*)d_in[2];        // [1, 128]
    const float* b1 = (const float*)d_in[3];        // [128]
    const float* W2 = (const float*)d_in[4];        // [128, 400]
    const float* b2 = (const float*)d_in[5];        // [400]
    float* out = (float*)d_out;                     // [400]

    const int* row = ei;
    const int* col = ei + N_EDGES;

    const int ET = N_EDGES / EPT;                   // 200000 threads

    k_zero   <<<(N_NODES + 255) / 256, 256>>>();
    k_deg    <<<(ET + 255) / 256, 256>>>(col);
    k_prep   <<<(N_NODES + 255) / 256, 256>>>(x);
    k_edges  <<<(ET + 255) / 256, 256>>>(row, col);
    k_accum_g<<<304, 128>>>(x, W1, b1);
    k_out    <<<2, 256>>>(W2, b2, out);
}

// round 4
// speedup vs baseline: 1.0894x; 1.0468x over previous
#include <cuda_runtime.h>

#define N_NODES 100000
#define N_EDGES 1600000
#define HIDDEN  128
#define OUT_DIM 400
#define EPT 8                       // edges per thread in scatter passes

// Scratch (__device__ globals; allocation-free rule)
__device__ float2 d_vd[N_NODES];    // {v accumulation, dinv}
__device__ float  d_deg[N_NODES];   // in-degree (real edges only)
__device__ float  d_a[N_NODES];     // dinv * x
__device__ float  d_u[N_NODES];     // sum over out-edges of dinv[col]
__device__ float  d_g[HIDDEN];      // sum_i t[i] * relu(s[i]*W1 + b1)

// 8B vector atomic: {v,dinv} += {addv, 0}; returns old dinv (element-wise
// atomic, so the +0.0 lane just reads dinv; dinv>0 so x+0 == x exactly).
__device__ __forceinline__ float atomv2_add_ret_dinv(float2* p, float addv) {
    float ox, oy;
    asm volatile("atom.global.add.v2.f32 {%0,%1}, [%2], {%3,%4};"
                 : "=f"(ox), "=f"(oy)
                 : "l"(p), "f"(addv), "f"(0.0f)
                 : "memory");
    return oy;
}

// ---------------------------------------------------------------------------
// Pass 0: zero deg/u/g (vd initialized by k_prep)
__global__ void k_zero() {
    int i = blockIdx.x * blockDim.x + threadIdx.x;
    if (i < N_NODES) { d_deg[i] = 0.0f; d_u[i] = 0.0f; }
    if (i < HIDDEN)  d_g[i] = 0.0f;
}

// Pass 1: in-degree histogram over destinations. 8 edges/thread.
__global__ void k_deg(const int* __restrict__ col) {
    int i = blockIdx.x * blockDim.x + threadIdx.x;
    if (i < N_EDGES / EPT) {
        const int4* c4 = (const int4*)col;
        int4 c0 = c4[2 * i];
        int4 c1 = c4[2 * i + 1];
        atomicAdd(&d_deg[c0.x], 1.0f);
        atomicAdd(&d_deg[c0.y], 1.0f);
        atomicAdd(&d_deg[c0.z], 1.0f);
        atomicAdd(&d_deg[c0.w], 1.0f);
        atomicAdd(&d_deg[c1.x], 1.0f);
        atomicAdd(&d_deg[c1.y], 1.0f);
        atomicAdd(&d_deg[c1.z], 1.0f);
        atomicAdd(&d_deg[c1.w], 1.0f);
    }
}

// Pass 2: dinv = rsqrt(deg+1) (self loop folded in); vd = {0, dinv}; a = dinv*x
__global__ void k_prep(const float* __restrict__ x) {
    int i = blockIdx.x * blockDim.x + threadIdx.x;
    if (i < N_NODES) {
        float dv = rsqrtf(d_deg[i] + 1.0f);
        d_vd[i] = make_float2(0.0f, dv);
        d_a[i]  = dv * x[i];
    }
}

// Pass 3: main edge pass, 3 random lane-ops per edge:
//   a_r = a[row]                       (gather)
//   {v[col],dinv[col]} += {a_r, 0}     (v2 atomic, returns dinv[col])
//   u[row] += dinv[col]                (red)
__global__ void k_edges(const int* __restrict__ row,
                        const int* __restrict__ col) {
    int i = blockIdx.x * blockDim.x + threadIdx.x;
    if (i >= N_EDGES / EPT) return;
    const int4* r4 = (const int4*)row;
    const int4* c4 = (const int4*)col;
    int4 r0 = r4[2 * i], r1 = r4[2 * i + 1];
    int4 c0 = c4[2 * i], c1 = c4[2 * i + 1];

    float a0 = __ldg(&d_a[r0.x]), a1 = __ldg(&d_a[r0.y]);
    float a2 = __ldg(&d_a[r0.z]), a3 = __ldg(&d_a[r0.w]);
    float a4 = __ldg(&d_a[r1.x]), a5 = __ldg(&d_a[r1.y]);
    float a6 = __ldg(&d_a[r1.z]), a7 = __ldg(&d_a[r1.w]);

    float dc0 = atomv2_add_ret_dinv(&d_vd[c0.x], a0);
    float dc1 = atomv2_add_ret_dinv(&d_vd[c0.y], a1);
    float dc2 = atomv2_add_ret_dinv(&d_vd[c0.z], a2);
    float dc3 = atomv2_add_ret_dinv(&d_vd[c0.w], a3);
    float dc4 = atomv2_add_ret_dinv(&d_vd[c1.x], a4);
    float dc5 = atomv2_add_ret_dinv(&d_vd[c1.y], a5);
    float dc6 = atomv2_add_ret_dinv(&d_vd[c1.z], a6);
    float dc7 = atomv2_add_ret_dinv(&d_vd[c1.w], a7);

    atomicAdd(&d_u[r0.x], dc0);
    atomicAdd(&d_u[r0.y], dc1);
    atomicAdd(&d_u[r0.z], dc2);
    atomicAdd(&d_u[r0.w], dc3);
    atomicAdd(&d_u[r1.x], dc4);
    atomicAdd(&d_u[r1.y], dc5);
    atomicAdd(&d_u[r1.z], dc6);
    atomicAdd(&d_u[r1.w], dc7);
}

// Pass 4: finalize s,t on the fly and accumulate
//   s[i] = dinv[i]*(v[i] + dinv[i]*x[i]);  t[i] = dinv[i]*(u[i] + dinv[i])
//   g[f] += sum_i t[i] * relu(s[i]*W1[f] + b1[f])
__global__ void k_accum_g(const float* __restrict__ x,
                          const float* __restrict__ W1,
                          const float* __restrict__ b1) {
    __shared__ float ss[128];
    __shared__ float st[128];
    int f = threadIdx.x;
    float w  = W1[f];
    float bb = b1[f];
    float acc = 0.0f;

    for (int base = blockIdx.x * 128; base < N_NODES; base += gridDim.x * 128) {
        int idx = base + f;
        __syncthreads();
        if (idx < N_NODES) {
            float2 vd = d_vd[idx];
            float dv = vd.y;
            ss[f] = dv * (vd.x + dv * x[idx]);
            st[f] = dv * (d_u[idx] + dv);
        } else {
            ss[f] = 0.0f;
            st[f] = 0.0f;
        }
        __syncthreads();
#pragma unroll 16
        for (int j = 0; j < 128; j++) {
            acc += st[j] * fmaxf(fmaf(ss[j], w, bb), 0.0f);
        }
    }
    atomicAdd(&d_g[f], acc);
}

// Pass 5: out[k] = b2[k] + (1/N) * sum_f g[f] * W2[f, k]
__global__ void k_out(const float* __restrict__ W2,
                      const float* __restrict__ b2,
                      float* __restrict__ out) {
    __shared__ float gs[HIDDEN];
    if (threadIdx.x < HIDDEN) gs[threadIdx.x] = d_g[threadIdx.x];
    __syncthreads();
    int k = blockIdx.x * blockDim.x + threadIdx.x;
    if (k < OUT_DIM) {
        float acc = 0.0f;
#pragma unroll 16
        for (int f = 0; f < HIDDEN; f++) {
            acc = fmaf(gs[f], W2[f * OUT_DIM + k], acc);
        }
        out[k] = b2[k] + acc * (1.0f / (float)N_NODES);
    }
}

// ---------------------------------------------------------------------------
extern "C" void kernel_launch(void* const* d_in, const int* in_sizes, int n_in,
                              void* d_out, int out_size) {
    const float* x  = (const float*)d_in[0];        // [N, 1]
    const int*   ei = (const int*)d_in[1];          // [2, E]: row then col
    const float* W1 = (const float*)d_in[2];        // [1, 128]
    const float* b1 = (const float*)d_in[3];        // [128]
    const float* W2 = (const float*)d_in[4];        // [128, 400]
    const float* b2 = (const float*)d_in[5];        // [400]
    float* out = (float*)d_out;                     // [400]

    const int* row = ei;
    const int* col = ei + N_EDGES;

    const int ET = N_EDGES / EPT;                   // 200000 threads

    k_zero   <<<(N_NODES + 255) / 256, 256>>>();
    k_deg    <<<(ET + 255) / 256, 256>>>(col);
    k_prep   <<<(N_NODES + 255) / 256, 256>>>(x);
    k_edges  <<<(ET + 255) / 256, 256>>>(row, col);
    k_accum_g<<<304, 128>>>(x, W1, b1);
    k_out    <<<2, 256>>>(W2, b2, out);
}